// round 13
// baseline (speedup 1.0000x reference)
#include <cuda_runtime.h>
#include <cstdint>
#include <cfloat>
#include <math.h>

#define NX 12288
#define NYTOT 12288
#define DD 256
#define KSEL 30
#define SPLITS 3
#define NYS (NYTOT / SPLITS)      // 4096
#define BM 128
#define BN 128
#define BKC 16
#define NST (DD / BKC)            // 16 k-stages
#define CSTR 132                  // Cs row stride (floats)

// scratch (no allocations allowed)
__device__ __align__(16) float g_Xn[NX * DD];
__device__ __align__(16) float g_Yn[NYTOT * DD];
__device__ float g_pv[SPLITS * 2 * KSEL * NX];   // [l][e][row] coalesced for merge
__device__ int   g_pi[SPLITS * 2 * KSEL * NX];
__device__ int   g_dummy_sink;

// ---------------------------------------------------------------------------
// Row-normalize (validated R8-B numerics — DO NOT CHANGE).
// ---------------------------------------------------------------------------
__global__ __launch_bounds__(128)
void norm_kernel(const float* __restrict__ X, const float* __restrict__ Y) {
    __shared__ float sw[4];
    __shared__ float smv;
    int row = blockIdx.x;
    const float* src;
    float* dst;
    if (row < NX) { src = X + (size_t)row * DD; dst = g_Xn + (size_t)row * DD; }
    else { int r = row - NX; src = Y + (size_t)r * DD; dst = g_Yn + (size_t)r * DD; }

    int t = threadIdx.x;
    int lane = t & 31;
    int warp = t >> 5;

    float2 e = *(const float2*)(src + 2 * t);
    float p = __fadd_rn(__fmul_rn(e.x, e.x), __fmul_rn(e.y, e.y));
    #pragma unroll
    for (int o = 16; o > 0; o >>= 1)
        p = __fadd_rn(p, __shfl_xor_sync(0xffffffffu, p, o));
    if (lane == 0) sw[warp] = p;
    __syncthreads();
    if (warp == 0) {
        float v = (lane < 4) ? sw[lane] : 0.0f;
        #pragma unroll
        for (int o = 16; o > 0; o >>= 1)
            v = __fadd_rn(v, __shfl_xor_sync(0xffffffffu, v, o));
        if (lane == 0)
            smv = fmaxf(__fsqrt_rn(v), 1e-8f);
    }
    __syncthreads();
    float inv = __fdiv_rn(1.0f, smv);
    float2 o;
    o.x = __fmul_rn(e.x, inv);
    o.y = __fmul_rn(e.y, inv);
    *(float2*)(dst + 2 * t) = o;
}

// Tiny dummy kernel: shifts the profiler's capture slot so that the 4th
// launch in the stream is simtopk_kernel. Deterministic, negligible cost.
__global__ void dummy_kernel(int tag) {
    if (threadIdx.x == 0 && blockIdx.x == 0)
        g_dummy_sink = tag;
}

// ---------------------------------------------------------------------------
// Fused SGEMM (128x128 tile, BK=16, fp32) + running per-row top-30.
// R9-exact structure (best known): LDG-staged double-buffered smem,
// conflict-free LDS.128 fragments, single ascending-k FMA chain.
// ---------------------------------------------------------------------------
__global__ __launch_bounds__(256, 2)
void simtopk_kernel() {
    extern __shared__ float sm[];
    float* As = sm;                     // [2][BKC][BM]
    float* Bs = sm + 2 * BKC * BM;      // [2][BKC][BN]
    float* Cs = sm;                     // [BM][CSTR] aliases (sync-separated)

    const int t = threadIdx.x;
    const int mbase = blockIdx.x * BM;
    const int sp = blockIdx.y;
    const int tx = t & 15;
    const int ty = t >> 4;

    const int lr = t & 127;
    const int lh = t >> 7;

    const int lrow = t >> 1;            // global-load row (0..127)
    const int lk8  = (t & 1) * 8;       // k-offset of this thread's 8-wide slab

    const int r0 = ty * 4, r1 = 64 + ty * 4;
    const int c0 = tx * 4, c1 = 64 + tx * 4;

    float kv[KSEL];
    int   ki[KSEL];
    #pragma unroll
    for (int j = 0; j < KSEL; j++) { kv[j] = -FLT_MAX; ki[j] = 0x7fffffff; }
    float kth = -FLT_MAX;

    const float* Aptr = g_Xn + (size_t)(mbase + lrow) * DD + lk8;

    #pragma unroll 1
    for (int nt = 0; nt < NYS / BN; nt++) {
        const int nbase = sp * NYS + nt * BN;
        const float* Bptr = g_Yn + (size_t)(nbase + lrow) * DD + lk8;

        float acc[8][8];
        #pragma unroll
        for (int i = 0; i < 8; i++)
            #pragma unroll
            for (int j = 0; j < 8; j++) acc[i][j] = 0.0f;

        // stage 0 fill
        {
            float4 aa = *(const float4*)(Aptr);
            float4 ab = *(const float4*)(Aptr + 4);
            float4 ba = *(const float4*)(Bptr);
            float4 bb = *(const float4*)(Bptr + 4);
            As[(lk8 + 0) * BM + lrow] = aa.x;
            As[(lk8 + 1) * BM + lrow] = aa.y;
            As[(lk8 + 2) * BM + lrow] = aa.z;
            As[(lk8 + 3) * BM + lrow] = aa.w;
            As[(lk8 + 4) * BM + lrow] = ab.x;
            As[(lk8 + 5) * BM + lrow] = ab.y;
            As[(lk8 + 6) * BM + lrow] = ab.z;
            As[(lk8 + 7) * BM + lrow] = ab.w;
            Bs[(lk8 + 0) * BN + lrow] = ba.x;
            Bs[(lk8 + 1) * BN + lrow] = ba.y;
            Bs[(lk8 + 2) * BN + lrow] = ba.z;
            Bs[(lk8 + 3) * BN + lrow] = ba.w;
            Bs[(lk8 + 4) * BN + lrow] = bb.x;
            Bs[(lk8 + 5) * BN + lrow] = bb.y;
            Bs[(lk8 + 6) * BN + lrow] = bb.z;
            Bs[(lk8 + 7) * BN + lrow] = bb.w;
        }
        __syncthreads();

        #pragma unroll 1
        for (int ksg = 0; ksg < NST; ksg++) {
            float4 naa, nab, nba, nbb;
            const bool more = (ksg + 1 < NST);
            if (more) {
                naa = *(const float4*)(Aptr + (ksg + 1) * BKC);
                nab = *(const float4*)(Aptr + (ksg + 1) * BKC + 4);
                nba = *(const float4*)(Bptr + (ksg + 1) * BKC);
                nbb = *(const float4*)(Bptr + (ksg + 1) * BKC + 4);
            }
            const float* Ac = As + (ksg & 1) * BKC * BM;
            const float* Bc = Bs + (ksg & 1) * BKC * BN;
            #pragma unroll
            for (int kk = 0; kk < BKC; kk++) {
                float a[8], b[8];
                *(float4*)(a)     = *(const float4*)(Ac + kk * BM + r0);
                *(float4*)(a + 4) = *(const float4*)(Ac + kk * BM + r1);
                *(float4*)(b)     = *(const float4*)(Bc + kk * BN + c0);
                *(float4*)(b + 4) = *(const float4*)(Bc + kk * BN + c1);
                #pragma unroll
                for (int i = 0; i < 8; i++)
                    #pragma unroll
                    for (int j = 0; j < 8; j++)
                        acc[i][j] = __fmaf_rn(a[i], b[j], acc[i][j]);
            }
            if (more) {
                float* An = As + ((ksg + 1) & 1) * BKC * BM;
                float* Bn = Bs + ((ksg + 1) & 1) * BKC * BN;
                An[(lk8 + 0) * BM + lrow] = naa.x;
                An[(lk8 + 1) * BM + lrow] = naa.y;
                An[(lk8 + 2) * BM + lrow] = naa.z;
                An[(lk8 + 3) * BM + lrow] = naa.w;
                An[(lk8 + 4) * BM + lrow] = nab.x;
                An[(lk8 + 5) * BM + lrow] = nab.y;
                An[(lk8 + 6) * BM + lrow] = nab.z;
                An[(lk8 + 7) * BM + lrow] = nab.w;
                Bn[(lk8 + 0) * BN + lrow] = nba.x;
                Bn[(lk8 + 1) * BN + lrow] = nba.y;
                Bn[(lk8 + 2) * BN + lrow] = nba.z;
                Bn[(lk8 + 3) * BN + lrow] = nba.w;
                Bn[(lk8 + 4) * BN + lrow] = nbb.x;
                Bn[(lk8 + 5) * BN + lrow] = nbb.y;
                Bn[(lk8 + 6) * BN + lrow] = nbb.z;
                Bn[(lk8 + 7) * BN + lrow] = nbb.w;
            }
            __syncthreads();
        }

        // stage C tile to smem
        #pragma unroll
        for (int i = 0; i < 8; i++) {
            int row = (i < 4) ? (r0 + i) : (r1 + i - 4);
            #pragma unroll
            for (int j = 0; j < 8; j++) {
                int col = (j < 4) ? (c0 + j) : (c1 + j - 4);
                Cs[row * CSTR + col] = acc[i][j];
            }
        }
        __syncthreads();

        // running top-k: thread scans 64 candidates of its row
        {
            const float4* crow4 = (const float4*)(Cs + lr * CSTR + lh * 64);
            const int gbase = nbase + lh * 64;
            #pragma unroll 1
            for (int j4 = 0; j4 < 16; j4++) {
                float4 v4 = crow4[j4];
                #pragma unroll
                for (int q = 0; q < 4; q++) {
                    float v = (q == 0) ? v4.x : (q == 1) ? v4.y : (q == 2) ? v4.z : v4.w;
                    if (v > kth) {
                        int p = KSEL - 1;
                        while (p > 0 && kv[p - 1] < v) {
                            kv[p] = kv[p - 1];
                            ki[p] = ki[p - 1];
                            p--;
                        }
                        kv[p] = v;
                        ki[p] = gbase + j4 * 4 + q;
                        kth = kv[KSEL - 1];
                    }
                }
            }
        }
        __syncthreads();   // before next tile overwrites Cs/As/Bs
    }

    // emit partial sorted list (coalesced-for-merge layout: [l][e][row])
    {
        const int row = mbase + lr;
        const int l = sp * 2 + lh;
        #pragma unroll 1
        for (int j = 0; j < KSEL; j++) {
            g_pv[(size_t)(l * KSEL + j) * NX + row] = kv[j];
            g_pi[(size_t)(l * KSEL + j) * NX + row] = ki[j];
        }
    }
}

// ---------------------------------------------------------------------------
// Merge 6 sorted partial lists per row -> final top-30; write values,u,v.
// Tie-break identical to jax.lax.top_k (value desc, index asc). Coalesced reads.
// ---------------------------------------------------------------------------
__global__ void merge_kernel(float* __restrict__ out) {
    int r = blockIdx.x * blockDim.x + threadIdx.x;
    if (r >= NX) return;
    float mv[KSEL];
    int   mi[KSEL];
    #pragma unroll
    for (int j = 0; j < KSEL; j++) { mv[j] = -FLT_MAX; mi[j] = 0x7fffffff; }

    for (int l = 0; l < SPLITS * 2; l++) {
        for (int e = 0; e < KSEL; e++) {
            float v = g_pv[(size_t)(l * KSEL + e) * NX + r];
            int idx = g_pi[(size_t)(l * KSEL + e) * NX + r];
            float lv = mv[KSEL - 1];
            int   li = mi[KSEL - 1];
            bool better = (v > lv) || (v == lv && idx < li);
            if (!better) break;   // sorted list: rest can't qualify
            int p = KSEL - 1;
            while (p > 0 && (v > mv[p - 1] || (v == mv[p - 1] && idx < mi[p - 1]))) {
                mv[p] = mv[p - 1];
                mi[p] = mi[p - 1];
                p--;
            }
            mv[p] = v;
            mi[p] = idx;
        }
    }

    const size_t NK = (size_t)NX * KSEL;
    #pragma unroll 1
    for (int j = 0; j < KSEL; j++) {
        out[(size_t)r * KSEL + j]          = mv[j];        // values
        out[NK + (size_t)r * KSEL + j]     = (float)r;     // u
        out[2 * NK + (size_t)r * KSEL + j] = (float)mi[j]; // v
    }
}

extern "C" void kernel_launch(void* const* d_in, const int* in_sizes, int n_in,
                              void* d_out, int out_size) {
    const float* X = (const float*)d_in[0];
    const float* Y = (const float*)d_in[1];
    float* out = (float*)d_out;

    const int smem_bytes = BM * CSTR * 4;   // 67584 (> 2*BKC*(BM+BN)*4 = 32768)
    cudaFuncSetAttribute(simtopk_kernel,
                         cudaFuncAttributeMaxDynamicSharedMemorySize, smem_bytes);

    norm_kernel<<<NX + NYTOT, 128>>>(X, Y);      // launch #1
    dummy_kernel<<<1, 32>>>(1);                  // launch #2
    dummy_kernel<<<1, 32>>>(2);                  // launch #3

    dim3 grid(NX / BM, SPLITS);
    simtopk_kernel<<<grid, 256, smem_bytes>>>(); // launch #4  <- profiler slot

    merge_kernel<<<(NX + 255) / 256, 256>>>(out); // launch #5
}

// round 14
// speedup vs baseline: 1.0341x; 1.0341x over previous
#include <cuda_runtime.h>
#include <cstdint>
#include <cfloat>
#include <math.h>

#define NX 12288
#define NYTOT 12288
#define DD 256
#define KSEL 30
#define SPLITS 3
#define NYS (NYTOT / SPLITS)      // 4096
#define BM 128
#define BN 128
#define BKC 16
#define NST (DD / BKC)            // 16 k-stages
#define CSTR 132                  // Cs row stride (floats)

// scratch (no allocations allowed)
__device__ __align__(16) float g_Xn[NX * DD];
__device__ __align__(16) float g_Yn[NYTOT * DD];
__device__ float g_pv[SPLITS * 2 * KSEL * NX];   // [l][e][row] coalesced for merge
__device__ int   g_pi[SPLITS * 2 * KSEL * NX];
__device__ int   g_dummy_sink;

// packed fp32x2 FMA: two independent correctly-rounded fp32 FMAs per instr.
// Lane0 = low 32 bits. Bitwise identical per-lane to scalar __fmaf_rn.
__device__ __forceinline__ void ffma2(unsigned long long& d,
                                      unsigned long long a2,
                                      unsigned long long b2) {
    asm("fma.rn.f32x2 %0, %1, %2, %0;" : "+l"(d) : "l"(a2), "l"(b2));
}
__device__ __forceinline__ unsigned long long pack2(float x) {
    unsigned long long r;
    asm("mov.b64 %0, {%1, %1};" : "=l"(r) : "f"(x));
    return r;
}

// ---------------------------------------------------------------------------
// Row-normalize (validated R8-B numerics — DO NOT CHANGE).
// ---------------------------------------------------------------------------
__global__ __launch_bounds__(128)
void norm_kernel(const float* __restrict__ X, const float* __restrict__ Y) {
    __shared__ float sw[4];
    __shared__ float smv;
    int row = blockIdx.x;
    const float* src;
    float* dst;
    if (row < NX) { src = X + (size_t)row * DD; dst = g_Xn + (size_t)row * DD; }
    else { int r = row - NX; src = Y + (size_t)r * DD; dst = g_Yn + (size_t)r * DD; }

    int t = threadIdx.x;
    int lane = t & 31;
    int warp = t >> 5;

    float2 e = *(const float2*)(src + 2 * t);
    float p = __fadd_rn(__fmul_rn(e.x, e.x), __fmul_rn(e.y, e.y));
    #pragma unroll
    for (int o = 16; o > 0; o >>= 1)
        p = __fadd_rn(p, __shfl_xor_sync(0xffffffffu, p, o));
    if (lane == 0) sw[warp] = p;
    __syncthreads();
    if (warp == 0) {
        float v = (lane < 4) ? sw[lane] : 0.0f;
        #pragma unroll
        for (int o = 16; o > 0; o >>= 1)
            v = __fadd_rn(v, __shfl_xor_sync(0xffffffffu, v, o));
        if (lane == 0)
            smv = fmaxf(__fsqrt_rn(v), 1e-8f);
    }
    __syncthreads();
    float inv = __fdiv_rn(1.0f, smv);
    float2 o;
    o.x = __fmul_rn(e.x, inv);
    o.y = __fmul_rn(e.y, inv);
    *(float2*)(dst + 2 * t) = o;
}

// Dummy launches keep simtopk at stream slot #4 (the profiler's capture slot).
__global__ void dummy_kernel(int tag) {
    if (threadIdx.x == 0 && blockIdx.x == 0)
        g_dummy_sink = tag;
}

// ---------------------------------------------------------------------------
// Fused SGEMM (128x128 tile, BK=16, fp32) + running per-row top-30.
// R9-exact staging; inner product via packed fma.rn.f32x2 (2 cols/instr).
// Per-element accumulation order unchanged (ascending k, single chain).
// ---------------------------------------------------------------------------
__global__ __launch_bounds__(256, 2)
void simtopk_kernel() {
    extern __shared__ float sm[];
    float* As = sm;                     // [2][BKC][BM]
    float* Bs = sm + 2 * BKC * BM;      // [2][BKC][BN]
    float* Cs = sm;                     // [BM][CSTR] aliases (sync-separated)

    const int t = threadIdx.x;
    const int mbase = blockIdx.x * BM;
    const int sp = blockIdx.y;
    const int tx = t & 15;
    const int ty = t >> 4;

    const int lr = t & 127;
    const int lh = t >> 7;

    const int lrow = t >> 1;            // global-load row (0..127)
    const int lk8  = (t & 1) * 8;       // k-offset of this thread's 8-wide slab

    const int r0 = ty * 4, r1 = 64 + ty * 4;
    const int c0 = tx * 4, c1 = 64 + tx * 4;

    float kv[KSEL];
    int   ki[KSEL];
    #pragma unroll
    for (int j = 0; j < KSEL; j++) { kv[j] = -FLT_MAX; ki[j] = 0x7fffffff; }
    float kth = -FLT_MAX;

    const float* Aptr = g_Xn + (size_t)(mbase + lrow) * DD + lk8;

    #pragma unroll 1
    for (int nt = 0; nt < NYS / BN; nt++) {
        const int nbase = sp * NYS + nt * BN;
        const float* Bptr = g_Yn + (size_t)(nbase + lrow) * DD + lk8;

        unsigned long long acc2[32];    // [i][jp]: packed cols (2 per entry)
        #pragma unroll
        for (int i = 0; i < 32; i++) acc2[i] = 0ull;   // two packed +0.0f

        // stage 0 fill
        {
            float4 aa = *(const float4*)(Aptr);
            float4 ab = *(const float4*)(Aptr + 4);
            float4 ba = *(const float4*)(Bptr);
            float4 bb = *(const float4*)(Bptr + 4);
            As[(lk8 + 0) * BM + lrow] = aa.x;
            As[(lk8 + 1) * BM + lrow] = aa.y;
            As[(lk8 + 2) * BM + lrow] = aa.z;
            As[(lk8 + 3) * BM + lrow] = aa.w;
            As[(lk8 + 4) * BM + lrow] = ab.x;
            As[(lk8 + 5) * BM + lrow] = ab.y;
            As[(lk8 + 6) * BM + lrow] = ab.z;
            As[(lk8 + 7) * BM + lrow] = ab.w;
            Bs[(lk8 + 0) * BN + lrow] = ba.x;
            Bs[(lk8 + 1) * BN + lrow] = ba.y;
            Bs[(lk8 + 2) * BN + lrow] = ba.z;
            Bs[(lk8 + 3) * BN + lrow] = ba.w;
            Bs[(lk8 + 4) * BN + lrow] = bb.x;
            Bs[(lk8 + 5) * BN + lrow] = bb.y;
            Bs[(lk8 + 6) * BN + lrow] = bb.z;
            Bs[(lk8 + 7) * BN + lrow] = bb.w;
        }
        __syncthreads();

        #pragma unroll 1
        for (int ksg = 0; ksg < NST; ksg++) {
            float4 naa, nab, nba, nbb;
            const bool more = (ksg + 1 < NST);
            if (more) {
                naa = *(const float4*)(Aptr + (ksg + 1) * BKC);
                nab = *(const float4*)(Aptr + (ksg + 1) * BKC + 4);
                nba = *(const float4*)(Bptr + (ksg + 1) * BKC);
                nbb = *(const float4*)(Bptr + (ksg + 1) * BKC + 4);
            }
            const float* Ac = As + (ksg & 1) * BKC * BM;
            const float* Bc = Bs + (ksg & 1) * BKC * BN;
            #pragma unroll
            for (int kk = 0; kk < BKC; kk++) {
                float4 af0 = *(const float4*)(Ac + kk * BM + r0);
                float4 af1 = *(const float4*)(Ac + kk * BM + r1);
                ulonglong2 bl = *(const ulonglong2*)(Bc + kk * BN + c0);
                ulonglong2 bh = *(const ulonglong2*)(Bc + kk * BN + c1);
                unsigned long long b2[4];
                b2[0] = bl.x; b2[1] = bl.y; b2[2] = bh.x; b2[3] = bh.y;
                unsigned long long a2[8];
                a2[0] = pack2(af0.x); a2[1] = pack2(af0.y);
                a2[2] = pack2(af0.z); a2[3] = pack2(af0.w);
                a2[4] = pack2(af1.x); a2[5] = pack2(af1.y);
                a2[6] = pack2(af1.z); a2[7] = pack2(af1.w);
                #pragma unroll
                for (int i = 0; i < 8; i++)
                    #pragma unroll
                    for (int jp = 0; jp < 4; jp++)
                        ffma2(acc2[i * 4 + jp], a2[i], b2[jp]);
            }
            if (more) {
                float* An = As + ((ksg + 1) & 1) * BKC * BM;
                float* Bn = Bs + ((ksg + 1) & 1) * BKC * BN;
                An[(lk8 + 0) * BM + lrow] = naa.x;
                An[(lk8 + 1) * BM + lrow] = naa.y;
                An[(lk8 + 2) * BM + lrow] = naa.z;
                An[(lk8 + 3) * BM + lrow] = naa.w;
                An[(lk8 + 4) * BM + lrow] = nab.x;
                An[(lk8 + 5) * BM + lrow] = nab.y;
                An[(lk8 + 6) * BM + lrow] = nab.z;
                An[(lk8 + 7) * BM + lrow] = nab.w;
                Bn[(lk8 + 0) * BN + lrow] = nba.x;
                Bn[(lk8 + 1) * BN + lrow] = nba.y;
                Bn[(lk8 + 2) * BN + lrow] = nba.z;
                Bn[(lk8 + 3) * BN + lrow] = nba.w;
                Bn[(lk8 + 4) * BN + lrow] = nbb.x;
                Bn[(lk8 + 5) * BN + lrow] = nbb.y;
                Bn[(lk8 + 6) * BN + lrow] = nbb.z;
                Bn[(lk8 + 7) * BN + lrow] = nbb.w;
            }
            __syncthreads();
        }

        // stage C tile to smem (packed pairs -> float2 stores)
        #pragma unroll
        for (int i = 0; i < 8; i++) {
            int row = (i < 4) ? (r0 + i) : (r1 + i - 4);
            #pragma unroll
            for (int jp = 0; jp < 4; jp++) {
                int col = (jp < 2) ? (c0 + 2 * jp) : (c1 + 2 * (jp - 2));
                *(float2*)(Cs + row * CSTR + col) = *(float2*)&acc2[i * 4 + jp];
            }
        }
        __syncthreads();

        // running top-k: thread scans 64 candidates of its row
        {
            const float4* crow4 = (const float4*)(Cs + lr * CSTR + lh * 64);
            const int gbase = nbase + lh * 64;
            #pragma unroll 1
            for (int j4 = 0; j4 < 16; j4++) {
                float4 v4 = crow4[j4];
                #pragma unroll
                for (int q = 0; q < 4; q++) {
                    float v = (q == 0) ? v4.x : (q == 1) ? v4.y : (q == 2) ? v4.z : v4.w;
                    if (v > kth) {
                        int p = KSEL - 1;
                        while (p > 0 && kv[p - 1] < v) {
                            kv[p] = kv[p - 1];
                            ki[p] = ki[p - 1];
                            p--;
                        }
                        kv[p] = v;
                        ki[p] = gbase + j4 * 4 + q;
                        kth = kv[KSEL - 1];
                    }
                }
            }
        }
        __syncthreads();   // before next tile overwrites Cs/As/Bs
    }

    // emit partial sorted list (coalesced-for-merge layout: [l][e][row])
    {
        const int row = mbase + lr;
        const int l = sp * 2 + lh;
        #pragma unroll 1
        for (int j = 0; j < KSEL; j++) {
            g_pv[(size_t)(l * KSEL + j) * NX + row] = kv[j];
            g_pi[(size_t)(l * KSEL + j) * NX + row] = ki[j];
        }
    }
}

// ---------------------------------------------------------------------------
// Merge 6 sorted partial lists per row -> final top-30; write values,u,v.
// Tie-break identical to jax.lax.top_k (value desc, index asc). Coalesced reads.
// ---------------------------------------------------------------------------
__global__ void merge_kernel(float* __restrict__ out) {
    int r = blockIdx.x * blockDim.x + threadIdx.x;
    if (r >= NX) return;
    float mv[KSEL];
    int   mi[KSEL];
    #pragma unroll
    for (int j = 0; j < KSEL; j++) { mv[j] = -FLT_MAX; mi[j] = 0x7fffffff; }

    for (int l = 0; l < SPLITS * 2; l++) {
        for (int e = 0; e < KSEL; e++) {
            float v = g_pv[(size_t)(l * KSEL + e) * NX + r];
            int idx = g_pi[(size_t)(l * KSEL + e) * NX + r];
            float lv = mv[KSEL - 1];
            int   li = mi[KSEL - 1];
            bool better = (v > lv) || (v == lv && idx < li);
            if (!better) break;   // sorted list: rest can't qualify
            int p = KSEL - 1;
            while (p > 0 && (v > mv[p - 1] || (v == mv[p - 1] && idx < mi[p - 1]))) {
                mv[p] = mv[p - 1];
                mi[p] = mi[p - 1];
                p--;
            }
            mv[p] = v;
            mi[p] = idx;
        }
    }

    const size_t NK = (size_t)NX * KSEL;
    #pragma unroll 1
    for (int j = 0; j < KSEL; j++) {
        out[(size_t)r * KSEL + j]          = mv[j];        // values
        out[NK + (size_t)r * KSEL + j]     = (float)r;     // u
        out[2 * NK + (size_t)r * KSEL + j] = (float)mi[j]; // v
    }
}

extern "C" void kernel_launch(void* const* d_in, const int* in_sizes, int n_in,
                              void* d_out, int out_size) {
    const float* X = (const float*)d_in[0];
    const float* Y = (const float*)d_in[1];
    float* out = (float*)d_out;

    const int smem_bytes = BM * CSTR * 4;   // 67584 (> 2*BKC*(BM+BN)*4 = 32768)
    cudaFuncSetAttribute(simtopk_kernel,
                         cudaFuncAttributeMaxDynamicSharedMemorySize, smem_bytes);

    norm_kernel<<<NX + NYTOT, 128>>>(X, Y);      // launch #1
    dummy_kernel<<<1, 32>>>(1);                  // launch #2
    dummy_kernel<<<1, 32>>>(2);                  // launch #3

    dim3 grid(NX / BM, SPLITS);
    simtopk_kernel<<<grid, 256, smem_bytes>>>(); // launch #4  <- profiler slot

    merge_kernel<<<(NX + 255) / 256, 256>>>(out); // launch #5
}